// round 5
// baseline (speedup 1.0000x reference)
#include <cuda_runtime.h>

#define GN    2048
#define NB    64
#define CI    32
#define CO    64
#define NK    3
#define ND    16
#define NNODE 2048

typedef unsigned long long ull;

// ---------------- scratch (device globals; no allocation) ----------------
__device__ float g_X  [GN*GN];      // x transposed to [n][b*CI+c]
__device__ float g_T1a[GN*GN];      // L_tilde @ X
__device__ float g_T2a[GN*GN];      // 2*L_tilde@T1a - X
__device__ float g_T1s[GN*GN];      // L_static @ X
__device__ float g_T2s[GN*GN];      // 2*L_static@T1s - X
__device__ float g_gc0[NNODE*NB*CO]; // lrelu(adaptive gconv)  [n][b][o]
__device__ float g_gc1[NNODE*NB*CO]; // lrelu(static gconv)    [n][b][o]
__device__ float g_sum0[NB*CO];
__device__ float g_sum1[NB*CO];
__device__ float g_M [NK*CI*CO];    // init_w @ gconv_w_k, [p=k*32+i][o]
__device__ float g_v [NK*CO];       // init_b @ gconv_w_k
__device__ float g_rs[NK*NNODE];    // row sums of cheb_polys
__device__ float g_s1[NB];
__device__ float g_s2[NB];

#define CP_ASYNC16(smem_u32, gptr) \
    asm volatile("cp.async.cg.shared.global [%0], [%1], 16;" :: "r"(smem_u32), "l"(gptr))
#define CP_COMMIT() asm volatile("cp.async.commit_group;")
#define CP_WAIT0()  asm volatile("cp.async.wait_group 0;")

// ---------------- tiny kernels ----------------
__global__ void transpose_x(const float* __restrict__ x) {
    int idx = blockIdx.x*blockDim.x + threadIdx.x;     // linear over [n][b][c]
    int c = idx & 31;
    int b = (idx >> 5) & 63;
    int n = idx >> 11;
    g_X[idx] = x[(b*NNODE + n)*CI + c];
}

__global__ void precompute_small(const float* __restrict__ init_w,
                                 const float* __restrict__ init_b,
                                 const float* __restrict__ gconv_w) {
    int tid = threadIdx.x;
    for (int e = tid; e < NK*CI*CO; e += 256) {
        int k = e / (CI*CO);
        int i = (e / CO) % CI;
        int o = e % CO;
        float s = 0.f;
        #pragma unroll 8
        for (int j = 0; j < CO; j++) s += init_w[i*CO + j] * gconv_w[(k*CO + j)*CO + o];
        g_M[e] = s;
    }
    if (tid < NK*CO) {
        int k = tid / CO, o = tid % CO;
        float s = 0.f;
        for (int j = 0; j < CO; j++) s += init_b[j] * gconv_w[(k*CO + j)*CO + o];
        g_v[tid] = s;
    }
}

__global__ void rowsums(const float* __restrict__ cheb) {
    int w = (blockIdx.x*blockDim.x + threadIdx.x) >> 5;  // row id over [k][n]
    int lane = threadIdx.x & 31;
    if (w >= NK*NNODE) return;
    const float* row = cheb + (size_t)w * GN;
    float s = 0.f;
    for (int m = lane; m < GN; m += 32) s += row[m];
    #pragma unroll
    for (int off = 16; off; off >>= 1) s += __shfl_xor_sync(0xffffffffu, s, off);
    if (lane == 0) g_rs[w] = s;
}

// ---------------- SGEMM: C = A(2048x2048) @ B(2048x2048), fp32 via fma.rn.f32x2 ----------------
// Double-buffered smem; A via register prefetch (needs transpose), B via cp.async.
// ONE __syncthreads per K-tile.
// STAGE 0: z=0: T1a = Lt @ X          z=1: T1s = Ls @ X
// STAGE 1: z=0: T2a = 2*Lt@T1a - X    z=1: T2s = 2*Ls@T1s - X
template<int STAGE>
__global__ __launch_bounds__(256, 2) void sgemm_stage(const float* __restrict__ A0,
                                                      const float* __restrict__ A1) {
    const bool adap = (blockIdx.z == 0);
    const float* __restrict__ A  = adap ? A0 : A1;
    const float* __restrict__ Bm = (STAGE==0) ? g_X : (adap ? g_T1a : g_T1s);
    float*       __restrict__ C  = (STAGE==0) ? (adap ? g_T1a : g_T1s)
                                              : (adap ? g_T2a : g_T2s);
    const float* __restrict__ Dm = g_X;   // only used in STAGE 1

    __shared__ alignas(16) float As[2][16][132];   // [buf][kk][row]
    __shared__ alignas(16) float Bs[2][16][132];   // [buf][kk][col]

    int tid  = threadIdx.x;
    int row0 = blockIdx.y * 128, col0 = blockIdx.x * 128;
    int aRow = tid >> 2, aCol = (tid & 3) << 2;   // A: 128 rows x 16 cols
    int bRow = tid >> 5, bCol = (tid & 31) << 2;  // B: 16 rows x 128 cols
    int ty = tid >> 4, tx = tid & 15;

    unsigned bs_u32 = (unsigned)__cvta_generic_to_shared(&Bs[0][0][0]);
    unsigned bs_dst0 = bs_u32 + (unsigned)(((bRow    )*132 + bCol) * 4);
    unsigned bs_dst1 = bs_u32 + (unsigned)(((bRow + 8)*132 + bCol) * 4);
    const unsigned bufBytes = 16u*132u*4u;

    ull acc[8][4];
    #pragma unroll
    for (int i = 0; i < 8; i++)
        #pragma unroll
        for (int j = 0; j < 4; j++) acc[i][j] = 0ull;

    float4 aV[2];

    // prologue: k-tile 0 -> buffer 0
    CP_ASYNC16(bs_dst0, Bm + (size_t)(bRow    )*GN + col0 + bCol);
    CP_ASYNC16(bs_dst1, Bm + (size_t)(bRow + 8)*GN + col0 + bCol);
    CP_COMMIT();
    #pragma unroll
    for (int h = 0; h < 2; h++)
        aV[h] = *(const float4*)(A + (size_t)(row0 + aRow + 64*h)*GN + aCol);
    #pragma unroll
    for (int h = 0; h < 2; h++) {
        int r = aRow + 64*h;
        As[0][aCol+0][r] = aV[h].x;
        As[0][aCol+1][r] = aV[h].y;
        As[0][aCol+2][r] = aV[h].z;
        As[0][aCol+3][r] = aV[h].w;
    }
    CP_WAIT0();
    __syncthreads();

    int buf = 0;
    for (int kt = 0; kt < GN; kt += 16) {
        int nxt = buf ^ 1;
        bool more = (kt + 16) < GN;
        if (more) {
            unsigned off = (unsigned)nxt * bufBytes;
            CP_ASYNC16(bs_dst0 + off, Bm + (size_t)(kt + 16 + bRow    )*GN + col0 + bCol);
            CP_ASYNC16(bs_dst1 + off, Bm + (size_t)(kt + 16 + bRow + 8)*GN + col0 + bCol);
            CP_COMMIT();
            #pragma unroll
            for (int h = 0; h < 2; h++)
                aV[h] = *(const float4*)(A + (size_t)(row0 + aRow + 64*h)*GN + kt + 16 + aCol);
        }

        #pragma unroll
        for (int kk = 0; kk < 16; kk++) {
            float4 a0 = *(const float4*)&As[buf][kk][4*ty];
            float4 a1 = *(const float4*)&As[buf][kk][64 + 4*ty];
            ull a2[8], b2[4];
            asm("mov.b64 %0, {%1, %1};" : "=l"(a2[0]) : "f"(a0.x));
            asm("mov.b64 %0, {%1, %1};" : "=l"(a2[1]) : "f"(a0.y));
            asm("mov.b64 %0, {%1, %1};" : "=l"(a2[2]) : "f"(a0.z));
            asm("mov.b64 %0, {%1, %1};" : "=l"(a2[3]) : "f"(a0.w));
            asm("mov.b64 %0, {%1, %1};" : "=l"(a2[4]) : "f"(a1.x));
            asm("mov.b64 %0, {%1, %1};" : "=l"(a2[5]) : "f"(a1.y));
            asm("mov.b64 %0, {%1, %1};" : "=l"(a2[6]) : "f"(a1.z));
            asm("mov.b64 %0, {%1, %1};" : "=l"(a2[7]) : "f"(a1.w));
            {
                const ulonglong2* p = (const ulonglong2*)&Bs[buf][kk][4*tx];
                ulonglong2 t0 = p[0];
                b2[0] = t0.x; b2[1] = t0.y;
                const ulonglong2* q = (const ulonglong2*)&Bs[buf][kk][64 + 4*tx];
                ulonglong2 t1 = q[0];
                b2[2] = t1.x; b2[3] = t1.y;
            }
            #pragma unroll
            for (int i = 0; i < 8; i++)
                #pragma unroll
                for (int j = 0; j < 4; j++)
                    asm("fma.rn.f32x2 %0, %1, %2, %0;"
                        : "+l"(acc[i][j]) : "l"(a2[i]), "l"(b2[j]));
        }

        if (more) {
            #pragma unroll
            for (int h = 0; h < 2; h++) {
                int r = aRow + 64*h;
                As[nxt][aCol+0][r] = aV[h].x;
                As[nxt][aCol+1][r] = aV[h].y;
                As[nxt][aCol+2][r] = aV[h].z;
                As[nxt][aCol+3][r] = aV[h].w;
            }
            CP_WAIT0();
        }
        __syncthreads();
        buf = nxt;
    }

    #pragma unroll
    for (int i = 0; i < 8; i++) {
        int gr = row0 + ((i < 4) ? (4*ty + i) : (64 + 4*ty + i - 4));
        #pragma unroll
        for (int half = 0; half < 2; half++) {
            int gc = col0 + 64*half + 4*tx;
            float lx, ly, hx, hy;
            asm("mov.b64 {%0,%1}, %2;" : "=f"(lx), "=f"(ly) : "l"(acc[i][2*half]));
            asm("mov.b64 {%0,%1}, %2;" : "=f"(hx), "=f"(hy) : "l"(acc[i][2*half+1]));
            float4 v = make_float4(lx, ly, hx, hy);
            if (STAGE == 1) {
                float4 d = *(const float4*)(Dm + (size_t)gr*GN + gc);
                v.x = 2.f*v.x - d.x; v.y = 2.f*v.y - d.y;
                v.z = 2.f*v.z - d.z; v.w = 2.f*v.w - d.w;
            }
            *(float4*)(C + (size_t)gr*GN + gc) = v;
        }
    }
}

// ---------------- per-node conv: [64 x 96] @ [96 x 64] with on-the-fly hyper-weights ----------------
// grid: (NNODE, 2); blockIdx.y==0 -> adaptive branch, ==1 -> static branch
__global__ __launch_bounds__(256) void node_conv(
    const float* __restrict__ emb,
    const float* __restrict__ wpool,
    const float* __restrict__ bpool,
    const float* __restrict__ gconv_b)
{
    __shared__ float sA[96][68];   // [p][b]
    __shared__ float sW[96][68];   // [p][o]
    __shared__ float sBias[64];
    __shared__ float sEmb[16];

    const bool ADAPTIVE = (blockIdx.y == 0);
    int n = blockIdx.x;
    int tid = threadIdx.x;
    const float* src0 = g_X + (size_t)n*GN;
    const float* src1 = (ADAPTIVE ? g_T1a : g_T1s) + (size_t)n*GN;
    const float* src2 = (ADAPTIVE ? g_T2a : g_T2s) + (size_t)n*GN;

    if (ADAPTIVE && tid < ND) sEmb[tid] = emb[n*ND + tid];
    __syncthreads();

    for (int e = tid; e < 2048; e += 256) {
        int b = e >> 5, i = e & 31;
        sA[i][b]      = src0[e];
        sA[32 + i][b] = src1[e];
        sA[64 + i][b] = src2[e];
    }
    if (ADAPTIVE) {
        for (int e = tid; e < 96*64; e += 256) {
            int p = e >> 6, o = e & 63;
            float s = 0.f;
            #pragma unroll
            for (int d = 0; d < ND; d++) s += sEmb[d] * wpool[d*6144 + p*64 + o];
            sW[p][o] = s;
        }
        if (tid < CO) {
            float s = 0.f;
            #pragma unroll
            for (int d = 0; d < ND; d++) s += sEmb[d] * bpool[d*CO + tid];
            sBias[tid] = s;
        }
    } else {
        for (int e = tid; e < 96*64; e += 256) sW[e >> 6][e & 63] = g_M[e];
        if (tid < CO) {
            sBias[tid] = g_rs[n]         * g_v[tid]
                       + g_rs[NNODE + n] * g_v[CO + tid]
                       + g_rs[2*NNODE+n] * g_v[2*CO + tid]
                       + gconv_b[tid];
        }
    }
    __syncthreads();

    int ty = tid >> 4, tx = tid & 15;   // 16 b-groups x 16 o-groups, each 4x4
    float acc[4][4] = {};
    #pragma unroll 4
    for (int p = 0; p < 96; p++) {
        float4 av = *(const float4*)&sA[p][4*ty];
        float4 wv = *(const float4*)&sW[p][4*tx];
        const float a[4] = {av.x, av.y, av.z, av.w};
        const float w[4] = {wv.x, wv.y, wv.z, wv.w};
        #pragma unroll
        for (int i = 0; i < 4; i++)
            #pragma unroll
            for (int j = 0; j < 4; j++) acc[i][j] += a[i] * w[j];
    }

    float* gcout = ADAPTIVE ? g_gc0 : g_gc1;
    #pragma unroll
    for (int i = 0; i < 4; i++) {
        int b = 4*ty + i;
        float4 v;
        float* vv = &v.x;
        #pragma unroll
        for (int j = 0; j < 4; j++) {
            float t = acc[i][j] + sBias[4*tx + j];
            t = (t >= 0.f) ? t : 0.01f*t;           // leaky relu
            vv[j] = t;
        }
        *(float4*)&gcout[((size_t)n*NB + b)*CO + 4*tx] = v;
    }
}

// ---------------- column reduction: g_sum[b][o] = sum_n g_gc[n][b][o] ----------------
// grid: (NB, 2); 256 threads: o = tid&63, n-chunk = tid>>6 (4 chunks)
__global__ __launch_bounds__(256) void col_reduce() {
    const bool ADAPTIVE = (blockIdx.y == 0);
    const float* __restrict__ src = ADAPTIVE ? g_gc0 : g_gc1;
    float* __restrict__ dst = ADAPTIVE ? g_sum0 : g_sum1;
    __shared__ float partial[4][64];
    int b = blockIdx.x;
    int o = threadIdx.x & 63;
    int chunk = threadIdx.x >> 6;
    float s = 0.f;
    for (int n = chunk*512; n < chunk*512 + 512; n++)
        s += src[((size_t)n*NB + b)*CO + o];
    partial[chunk][o] = s;
    __syncthreads();
    if (chunk == 0)
        dst[b*CO + o] = partial[0][o] + partial[1][o] + partial[2][o] + partial[3][o];
}

// ---------------- SelfAtt scalars ----------------
__global__ void att_scalars(const float* __restrict__ g1_fc1, const float* __restrict__ g1_fc2,
                            const float* __restrict__ g2_fc1, const float* __restrict__ g2_fc2) {
    int b = threadIdx.x;
    if (b >= NB) return;
    float h1[4] = {0,0,0,0}, h2[4] = {0,0,0,0};
    for (int c = 0; c < CO; c++) {
        float y0 = g_sum0[b*CO + c] * (1.f/NNODE);
        float y1 = g_sum1[b*CO + c] * (1.f/NNODE);
        #pragma unroll
        for (int r = 0; r < 4; r++) {
            h1[r] += y0 * g1_fc1[c*4 + r];
            h2[r] += y1 * g2_fc1[c*4 + r];
        }
    }
    float z1 = 0.f, z2 = 0.f;
    #pragma unroll
    for (int r = 0; r < 4; r++) {
        z1 += (h1[r] > 0.f ? h1[r] : 0.f) * g1_fc2[r];
        z2 += (h2[r] > 0.f ? h2[r] : 0.f) * g2_fc2[r];
    }
    g_s1[b] = fminf(fmaxf(z1*(1.f/6.f) + 0.5f, 0.f), 1.f);
    g_s2[b] = fminf(fmaxf(z2*(1.f/6.f) + 0.5f, 0.f), 1.f);
}

// ---------------- fused final output ----------------
__global__ void final_out(float* __restrict__ out) {
    int idx = blockIdx.x*blockDim.x + threadIdx.x;   // [b][n][o]
    int o = idx & 63;
    int n = (idx >> 6) & 2047;
    int b = idx >> 17;
    size_t src = ((size_t)n*NB + b)*CO + o;
    out[idx] = g_gc0[src]*g_s1[b] + g_gc1[src]*g_s2[b];
}

// ---------------- launch ----------------
extern "C" void kernel_launch(void* const* d_in, const int* in_sizes, int n_in,
                              void* d_out, int out_size) {
    const float* x       = (const float*)d_in[0];
    const float* emb     = (const float*)d_in[1];
    const float* Lt      = (const float*)d_in[2];
    const float* cheb    = (const float*)d_in[3];
    const float* wpool   = (const float*)d_in[4];
    const float* bpool   = (const float*)d_in[5];
    const float* init_w  = (const float*)d_in[6];
    const float* init_b  = (const float*)d_in[7];
    const float* gconv_w = (const float*)d_in[8];
    const float* gconv_b = (const float*)d_in[9];
    const float* g1_fc1  = (const float*)d_in[10];
    const float* g1_fc2  = (const float*)d_in[11];
    const float* g2_fc1  = (const float*)d_in[12];
    const float* g2_fc2  = (const float*)d_in[13];
    float* out = (float*)d_out;
    const float* Ls = cheb + (size_t)GN*GN;   // cheb_polys[1] == L_static

    transpose_x<<<(GN*GN)/256, 256>>>(x);
    precompute_small<<<1, 256>>>(init_w, init_b, gconv_w);
    rowsums<<<(NK*NNODE)/8, 256>>>(cheb);

    dim3 g(16, 16, 2);
    sgemm_stage<0><<<g, 256>>>(Lt, Ls);   // T1a, T1s
    sgemm_stage<1><<<g, 256>>>(Lt, Ls);   // T2a = 2*Lt@T1a - X, T2s = 2*Ls@T1s - X

    node_conv<<<dim3(NNODE, 2), 256>>>(emb, wpool, bpool, gconv_b);

    col_reduce<<<dim3(NB, 2), 256>>>();

    att_scalars<<<1, 64>>>(g1_fc1, g1_fc2, g2_fc1, g2_fc2);
    final_out<<<(GN*NB*CO)/256, 256>>>(out);
}

// round 17
// speedup vs baseline: 1.0312x; 1.0312x over previous
#include <cuda_runtime.h>
#include <cuda_bf16.h>

#define GN    2048
#define NB    64
#define CI    32
#define CO    64
#define NK    3
#define ND    16
#define NNODE 2048

typedef unsigned long long ull;

// ---------------- scratch (device globals; no allocation) ----------------
__device__ float g_X  [GN*GN];       // x transposed to [n][b*CI+c]
__device__ float g_T1a[GN*GN];       // L_tilde @ X
__device__ float g_T2a[GN*GN];       // 2*L_tilde@T1a - X
__device__ float g_T1s[GN*GN];       // L_static @ X
__device__ float g_T2s[GN*GN];       // 2*L_static@T1s - X
__device__ float g_gc0[NNODE*NB*CO]; // lrelu(adaptive gconv)  [n][b][o]
__device__ float g_gc1[NNODE*NB*CO]; // lrelu(static gconv)    [n][b][o]
__device__ float g_sum0[NB*CO];
__device__ float g_sum1[NB*CO];
__device__ float g_M [NK*CI*CO];
__device__ float g_v [NK*CO];
__device__ float g_rs[NK*NNODE];
__device__ float g_s1[NB];
__device__ float g_s2[NB];

// bf16 hi/lo split operands for tensor-core GEMMs
__device__ __nv_bfloat16 g_LtH[GN*GN], g_LtL[GN*GN];     // A: L_tilde (K-major rows)
__device__ __nv_bfloat16 g_LsH[GN*GN], g_LsL[GN*GN];     // A: L_static
__device__ __nv_bfloat16 g_XTh[GN*GN], g_XTl[GN*GN];     // B^T: X^T [col][m]
__device__ __nv_bfloat16 g_T1aTh[GN*GN], g_T1aTl[GN*GN]; // B^T: T1a^T
__device__ __nv_bfloat16 g_T1sTh[GN*GN], g_T1sTl[GN*GN]; // B^T: T1s^T

// ---------------- PTX helpers (family-agnostic sm_80-era ONLY) ----------------
__device__ __forceinline__ unsigned smem_u32(const void* p) {
    unsigned a;
    asm("{ .reg .u64 t; cvta.to.shared.u64 t, %1; cvt.u32.u64 %0, t; }" : "=r"(a) : "l"(p));
    return a;
}
#define CP_ASYNC16(smem32, gptr) \
    asm volatile("cp.async.cg.shared.global [%0], [%1], 16;" :: "r"(smem32), "l"(gptr))
#define CP_COMMIT() asm volatile("cp.async.commit_group;")
#define CP_WAIT0()  asm volatile("cp.async.wait_group 0;")
#define CP_WAIT1()  asm volatile("cp.async.wait_group 1;")

__device__ __forceinline__ void ldsm_x4(unsigned* r, unsigned addr) {
    asm volatile("ldmatrix.sync.aligned.m8n8.x4.shared.b16 {%0,%1,%2,%3}, [%4];"
        : "=r"(r[0]), "=r"(r[1]), "=r"(r[2]), "=r"(r[3]) : "r"(addr));
}
__device__ __forceinline__ void ldsm_x2(unsigned* r, unsigned addr) {
    asm volatile("ldmatrix.sync.aligned.m8n8.x2.shared.b16 {%0,%1}, [%2];"
        : "=r"(r[0]), "=r"(r[1]) : "r"(addr));
}
__device__ __forceinline__ void mma_bf16(float* d, const unsigned* a, const unsigned* b) {
    asm volatile("mma.sync.aligned.m16n8k16.row.col.f32.bf16.bf16.f32 "
        "{%0,%1,%2,%3}, {%4,%5,%6,%7}, {%8,%9}, {%0,%1,%2,%3};"
        : "+f"(d[0]), "+f"(d[1]), "+f"(d[2]), "+f"(d[3])
        : "r"(a[0]), "r"(a[1]), "r"(a[2]), "r"(a[3]), "r"(b[0]), "r"(b[1]));
}

// ---------------- tiny kernels ----------------
__global__ void transpose_x(const float* __restrict__ x) {
    int idx = blockIdx.x*blockDim.x + threadIdx.x;     // linear over [n][b][c]
    int c = idx & 31;
    int b = (idx >> 5) & 63;
    int n = idx >> 11;
    g_X[idx] = x[(b*NNODE + n)*CI + c];
}

// split fp32 -> bf16 hi/lo (no transpose), for A operands Lt/Ls
__global__ void split_A(const float* __restrict__ Lt, const float* __restrict__ Ls) {
    size_t i = (size_t)blockIdx.x*256 + threadIdx.x;
    const float* s = blockIdx.y ? Ls : Lt;
    __nv_bfloat16* h = blockIdx.y ? g_LsH : g_LtH;
    __nv_bfloat16* l = blockIdx.y ? g_LsL : g_LtL;
    float vv = s[i];
    __nv_bfloat16 hi = __float2bfloat16(vv);
    h[i] = hi;
    l[i] = __float2bfloat16(vv - __bfloat162float(hi));
}

// transpose + split: out[col][row] = split(in[row][col])
__global__ void transpose_split(int mode) {
    const float* in;
    __nv_bfloat16 *oh, *ol;
    if (mode == 0)            { in = g_X;   oh = g_XTh;   ol = g_XTl; }
    else if (blockIdx.z == 0) { in = g_T1a; oh = g_T1aTh; ol = g_T1aTl; }
    else                      { in = g_T1s; oh = g_T1sTh; ol = g_T1sTl; }
    __shared__ float t[32][33];
    int bx = blockIdx.x*32, by = blockIdx.y*32;
    int tx = threadIdx.x, ty = threadIdx.y;
    #pragma unroll
    for (int j = 0; j < 32; j += 8)
        t[ty+j][tx] = in[(size_t)(by+ty+j)*GN + bx + tx];
    __syncthreads();
    #pragma unroll
    for (int j = 0; j < 32; j += 8) {
        float vv = t[tx][ty+j];
        __nv_bfloat16 hi = __float2bfloat16(vv);
        size_t o = (size_t)(bx+ty+j)*GN + by + tx;
        oh[o] = hi;
        ol[o] = __float2bfloat16(vv - __bfloat162float(hi));
    }
}

__global__ void precompute_small(const float* __restrict__ init_w,
                                 const float* __restrict__ init_b,
                                 const float* __restrict__ gconv_w) {
    int tid = threadIdx.x;
    for (int e = tid; e < NK*CI*CO; e += 256) {
        int k = e / (CI*CO);
        int i = (e / CO) % CI;
        int o = e % CO;
        float s = 0.f;
        #pragma unroll 8
        for (int j = 0; j < CO; j++) s += init_w[i*CO + j] * gconv_w[(k*CO + j)*CO + o];
        g_M[e] = s;
    }
    if (tid < NK*CO) {
        int k = tid / CO, o = tid % CO;
        float s = 0.f;
        for (int j = 0; j < CO; j++) s += init_b[j] * gconv_w[(k*CO + j)*CO + o];
        g_v[tid] = s;
    }
}

__global__ void rowsums(const float* __restrict__ cheb) {
    int w = (blockIdx.x*blockDim.x + threadIdx.x) >> 5;
    int lane = threadIdx.x & 31;
    if (w >= NK*NNODE) return;
    const float* row = cheb + (size_t)w * GN;
    float s = 0.f;
    for (int m = lane; m < GN; m += 32) s += row[m];
    #pragma unroll
    for (int off = 16; off; off >>= 1) s += __shfl_xor_sync(0xffffffffu, s, off);
    if (lane == 0) g_rs[w] = s;
}

// ---------------- mma.sync GEMM: C = A(2048x2048) @ B(2048x2048) ----------------
// 3-product split-fp32: C = Ah*Bh + Ah*Bl + Al*Bh, fp32 accum in registers.
// 128x128 tile/CTA; 8 warps each 64x32; K chunks of 32; cp.async double-buffer.
// smem tile: 128 rows x 40 bf16 (padded; 80B row -> conflict-free ldmatrix).
#define ROWP 40
#define TEN_BYTES (128*ROWP*2)   // 10240 per tensor tile
#define BUFB (4*TEN_BYTES)       // Ah, Al, BTh, BTl

__device__ __forceinline__ void load_tile40(unsigned dstBase,
                                            const __nv_bfloat16* __restrict__ src,
                                            int rowBase, int kElem, int tid) {
    #pragma unroll
    for (int i = 0; i < 2; i++) {
        int ch = tid + i*256;           // 512 chunks of 16B
        int r = ch >> 2, c = ch & 3;
        unsigned dst = dstBase + (unsigned)(r*80 + c*16);
        CP_ASYNC16(dst, (const char*)(src + (((size_t)(rowBase + r)) << 11) + kElem + c*8));
    }
}

template<int STAGE>
__global__ __launch_bounds__(256, 2) void mma_gemm() {
    extern __shared__ char dsm[];
    int tid = threadIdx.x, wid = tid >> 5, lane = tid & 31;
    const bool adap = (blockIdx.z == 0);
    int row0 = blockIdx.y * 128, col0 = blockIdx.x * 128;
    int warp_m = wid & 1, warp_n = wid >> 1;     // 2 x 4 warp grid

    const __nv_bfloat16* Ah = adap ? g_LtH : g_LsH;
    const __nv_bfloat16* Al = adap ? g_LtL : g_LsL;
    const __nv_bfloat16 *Bh, *Bl;
    if (STAGE == 0) { Bh = g_XTh; Bl = g_XTl; }
    else            { Bh = adap ? g_T1aTh : g_T1sTh; Bl = adap ? g_T1aTl : g_T1sTl; }
    float* C = (STAGE == 0) ? (adap ? g_T1a : g_T1s) : (adap ? g_T2a : g_T2s);

    unsigned sb = (smem_u32(dsm) + 127u) & ~127u;

    float acc[4][4][4];
    #pragma unroll
    for (int mi = 0; mi < 4; mi++)
        #pragma unroll
        for (int ni = 0; ni < 4; ni++)
            #pragma unroll
            for (int q = 0; q < 4; q++) acc[mi][ni][q] = 0.f;

    // prologue: chunk 0 -> buf0
    load_tile40(sb + 0*TEN_BYTES, Ah, row0, 0, tid);
    load_tile40(sb + 1*TEN_BYTES, Al, row0, 0, tid);
    load_tile40(sb + 2*TEN_BYTES, Bh, col0, 0, tid);
    load_tile40(sb + 3*TEN_BYTES, Bl, col0, 0, tid);
    CP_COMMIT();

    // ldmatrix lane addressing (constant per thread)
    int aRow = lane & 15, aKof = (lane >> 4) * 8;
    int bRow = lane & 7,  bKof = ((lane >> 3) & 1) * 8;

    for (int kt = 0; kt < 64; kt++) {
        unsigned base = sb + (unsigned)(kt & 1) * BUFB;
        if (kt < 63) {
            unsigned nb = sb + (unsigned)((kt + 1) & 1) * BUFB;
            int kc = (kt + 1) * 32;
            load_tile40(nb + 0*TEN_BYTES, Ah, row0, kc, tid);
            load_tile40(nb + 1*TEN_BYTES, Al, row0, kc, tid);
            load_tile40(nb + 2*TEN_BYTES, Bh, col0, kc, tid);
            load_tile40(nb + 3*TEN_BYTES, Bl, col0, kc, tid);
            CP_COMMIT();
            CP_WAIT1();
        } else {
            CP_WAIT0();
        }
        __syncthreads();

        #pragma unroll
        for (int ks = 0; ks < 2; ks++) {
            int k0 = ks * 16;
            unsigned ah[4][4], al[4][4], bb[4][2];
            #pragma unroll
            for (int mi = 0; mi < 4; mi++) {
                unsigned ad = base + (unsigned)((warp_m*64 + mi*16 + aRow)*80 + (k0 + aKof)*2);
                ldsm_x4(ah[mi], ad);
                ldsm_x4(al[mi], ad + TEN_BYTES);
            }
            #pragma unroll
            for (int ni = 0; ni < 4; ni++) {
                unsigned bd = base + 2*TEN_BYTES
                            + (unsigned)((warp_n*32 + ni*8 + bRow)*80 + (k0 + bKof)*2);
                ldsm_x2(bb[ni], bd);
            }
            #pragma unroll
            for (int mi = 0; mi < 4; mi++)
                #pragma unroll
                for (int ni = 0; ni < 4; ni++) {
                    mma_bf16(acc[mi][ni], ah[mi], bb[ni]);   // Ah*Bh
                    mma_bf16(acc[mi][ni], al[mi], bb[ni]);   // Al*Bh
                }
            #pragma unroll
            for (int ni = 0; ni < 4; ni++) {
                unsigned bd = base + 3*TEN_BYTES
                            + (unsigned)((warp_n*32 + ni*8 + bRow)*80 + (k0 + bKof)*2);
                ldsm_x2(bb[ni], bd);
            }
            #pragma unroll
            for (int mi = 0; mi < 4; mi++)
                #pragma unroll
                for (int ni = 0; ni < 4; ni++)
                    mma_bf16(acc[mi][ni], ah[mi], bb[ni]);   // Ah*Bl
        }
        __syncthreads();
    }

    // epilogue
    int r0 = row0 + warp_m*64, c0 = col0 + warp_n*32;
    int rofs = lane >> 2, cofs = 2*(lane & 3);
    #pragma unroll
    for (int mi = 0; mi < 4; mi++)
        #pragma unroll
        for (int ni = 0; ni < 4; ni++) {
            int rr = r0 + mi*16 + rofs;
            int cc = c0 + ni*8 + cofs;
            float2 v0 = make_float2(acc[mi][ni][0], acc[mi][ni][1]);
            float2 v1 = make_float2(acc[mi][ni][2], acc[mi][ni][3]);
            if (STAGE == 1) {
                float2 x0 = *(const float2*)&g_X[(size_t)rr*GN + cc];
                float2 x1 = *(const float2*)&g_X[(size_t)(rr+8)*GN + cc];
                v0.x = 2.f*v0.x - x0.x; v0.y = 2.f*v0.y - x0.y;
                v1.x = 2.f*v1.x - x1.x; v1.y = 2.f*v1.y - x1.y;
            }
            *(float2*)&C[(size_t)rr*GN + cc]     = v0;
            *(float2*)&C[(size_t)(rr+8)*GN + cc] = v1;
        }
}

// ---------------- per-node conv: [64 x 96] @ [96 x 64] with on-the-fly hyper-weights ----------------
__global__ __launch_bounds__(256) void node_conv(
    const float* __restrict__ emb,
    const float* __restrict__ wpool,
    const float* __restrict__ bpool,
    const float* __restrict__ gconv_b)
{
    __shared__ float sA[96][68];
    __shared__ float sW[96][68];
    __shared__ float sBias[64];
    __shared__ float sEmb[16];

    const bool ADAPTIVE = (blockIdx.y == 0);
    int n = blockIdx.x;
    int tid = threadIdx.x;
    const float* src0 = g_X + (size_t)n*GN;
    const float* src1 = (ADAPTIVE ? g_T1a : g_T1s) + (size_t)n*GN;
    const float* src2 = (ADAPTIVE ? g_T2a : g_T2s) + (size_t)n*GN;

    if (ADAPTIVE && tid < ND) sEmb[tid] = emb[n*ND + tid];
    __syncthreads();

    for (int e = tid; e < 2048; e += 256) {
        int b = e >> 5, i = e & 31;
        sA[i][b]      = src0[e];
        sA[32 + i][b] = src1[e];
        sA[64 + i][b] = src2[e];
    }
    if (ADAPTIVE) {
        for (int e = tid; e < 96*64; e += 256) {
            int p = e >> 6, o = e & 63;
            float s = 0.f;
            #pragma unroll
            for (int d = 0; d < ND; d++) s += sEmb[d] * wpool[d*6144 + p*64 + o];
            sW[p][o] = s;
        }
        if (tid < CO) {
            float s = 0.f;
            #pragma unroll
            for (int d = 0; d < ND; d++) s += sEmb[d] * bpool[d*CO + tid];
            sBias[tid] = s;
        }
    } else {
        for (int e = tid; e < 96*64; e += 256) sW[e >> 6][e & 63] = g_M[e];
        if (tid < CO) {
            sBias[tid] = g_rs[n]         * g_v[tid]
                       + g_rs[NNODE + n] * g_v[CO + tid]
                       + g_rs[2*NNODE+n] * g_v[2*CO + tid]
                       + gconv_b[tid];
        }
    }
    __syncthreads();

    int ty = tid >> 4, tx = tid & 15;
    float acc[4][4] = {};
    #pragma unroll 4
    for (int p = 0; p < 96; p++) {
        float4 av = *(const float4*)&sA[p][4*ty];
        float4 wv = *(const float4*)&sW[p][4*tx];
        const float a[4] = {av.x, av.y, av.z, av.w};
        const float w[4] = {wv.x, wv.y, wv.z, wv.w};
        #pragma unroll
        for (int i = 0; i < 4; i++)
            #pragma unroll
            for (int j = 0; j < 4; j++) acc[i][j] += a[i] * w[j];
    }

    float* gcout = ADAPTIVE ? g_gc0 : g_gc1;
    #pragma unroll
    for (int i = 0; i < 4; i++) {
        int b = 4*ty + i;
        float4 vv;
        float* vp = &vv.x;
        #pragma unroll
        for (int j = 0; j < 4; j++) {
            float t = acc[i][j] + sBias[4*tx + j];
            t = (t >= 0.f) ? t : 0.01f*t;
            vp[j] = t;
        }
        *(float4*)&gcout[((size_t)n*NB + b)*CO + 4*tx] = vv;
    }
}

// ---------------- column reduction ----------------
__global__ __launch_bounds__(256) void col_reduce() {
    const bool ADAPTIVE = (blockIdx.y == 0);
    const float* __restrict__ src = ADAPTIVE ? g_gc0 : g_gc1;
    float* __restrict__ dst = ADAPTIVE ? g_sum0 : g_sum1;
    __shared__ float partial[4][64];
    int b = blockIdx.x;
    int o = threadIdx.x & 63;
    int chunk = threadIdx.x >> 6;
    float s = 0.f;
    for (int n = chunk*512; n < chunk*512 + 512; n++)
        s += src[((size_t)n*NB + b)*CO + o];
    partial[chunk][o] = s;
    __syncthreads();
    if (chunk == 0)
        dst[b*CO + o] = partial[0][o] + partial[1][o] + partial[2][o] + partial[3][o];
}

// ---------------- SelfAtt scalars ----------------
__global__ void att_scalars(const float* __restrict__ g1_fc1, const float* __restrict__ g1_fc2,
                            const float* __restrict__ g2_fc1, const float* __restrict__ g2_fc2) {
    int b = threadIdx.x;
    if (b >= NB) return;
    float h1[4] = {0,0,0,0}, h2[4] = {0,0,0,0};
    for (int c = 0; c < CO; c++) {
        float y0 = g_sum0[b*CO + c] * (1.f/NNODE);
        float y1 = g_sum1[b*CO + c] * (1.f/NNODE);
        #pragma unroll
        for (int r = 0; r < 4; r++) {
            h1[r] += y0 * g1_fc1[c*4 + r];
            h2[r] += y1 * g2_fc1[c*4 + r];
        }
    }
    float z1 = 0.f, z2 = 0.f;
    #pragma unroll
    for (int r = 0; r < 4; r++) {
        z1 += (h1[r] > 0.f ? h1[r] : 0.f) * g1_fc2[r];
        z2 += (h2[r] > 0.f ? h2[r] : 0.f) * g2_fc2[r];
    }
    g_s1[b] = fminf(fmaxf(z1*(1.f/6.f) + 0.5f, 0.f), 1.f);
    g_s2[b] = fminf(fmaxf(z2*(1.f/6.f) + 0.5f, 0.f), 1.f);
}

// ---------------- fused final output ----------------
__global__ void final_out(float* __restrict__ out) {
    int idx = blockIdx.x*blockDim.x + threadIdx.x;   // [b][n][o]
    int o = idx & 63;
    int n = (idx >> 6) & 2047;
    int b = idx >> 17;
    size_t src = ((size_t)n*NB + b)*CO + o;
    out[idx] = g_gc0[src]*g_s1[b] + g_gc1[src]*g_s2[b];
}

// ---------------- launch ----------------
extern "C" void kernel_launch(void* const* d_in, const int* in_sizes, int n_in,
                              void* d_out, int out_size) {
    const float* x       = (const float*)d_in[0];
    const float* emb     = (const float*)d_in[1];
    const float* Lt      = (const float*)d_in[2];
    const float* cheb    = (const float*)d_in[3];
    const float* wpool   = (const float*)d_in[4];
    const float* bpool   = (const float*)d_in[5];
    const float* init_w  = (const float*)d_in[6];
    const float* init_b  = (const float*)d_in[7];
    const float* gconv_w = (const float*)d_in[8];
    const float* gconv_b = (const float*)d_in[9];
    const float* g1_fc1  = (const float*)d_in[10];
    const float* g1_fc2  = (const float*)d_in[11];
    const float* g2_fc1  = (const float*)d_in[12];
    const float* g2_fc2  = (const float*)d_in[13];
    float* out = (float*)d_out;
    const float* Ls = cheb + (size_t)GN*GN;   // cheb_polys[1] == L_static

    const int SMEM_DYN = 2*BUFB + 256;   // ~82 KB dynamic
    cudaFuncSetAttribute(mma_gemm<0>, cudaFuncAttributeMaxDynamicSharedMemorySize, SMEM_DYN);
    cudaFuncSetAttribute(mma_gemm<1>, cudaFuncAttributeMaxDynamicSharedMemorySize, SMEM_DYN);

    transpose_x<<<(GN*GN)/256, 256>>>(x);
    split_A<<<dim3((GN*GN)/256, 2), 256>>>(Lt, Ls);
    transpose_split<<<dim3(64, 64), dim3(32, 8)>>>(0);           // X^T hi/lo
    precompute_small<<<1, 256>>>(init_w, init_b, gconv_w);
    rowsums<<<(NK*NNODE)/8, 256>>>(cheb);

    dim3 g(16, 16, 2);
    mma_gemm<0><<<g, 256, SMEM_DYN>>>();                         // T1a, T1s (fp32)
    transpose_split<<<dim3(64, 64, 2), dim3(32, 8)>>>(1);        // T1^T hi/lo
    mma_gemm<1><<<g, 256, SMEM_DYN>>>();                         // T2 = 2*L@T1 - X

    node_conv<<<dim3(NNODE, 2), 256>>>(emb, wpool, bpool, gconv_b);
    col_reduce<<<dim3(NB, 2), 256>>>();
    att_scalars<<<1, 64>>>(g1_fc1, g1_fc2, g2_fc1, g2_fc2);
    final_out<<<(GN*NB*CO)/256, 256>>>(out);
}